// round 15
// baseline (speedup 1.0000x reference)
#include <cuda_runtime.h>
#include <cuda_bf16.h>
#include <cstdint>

#define N_NODES   30000
#define N_EDGES   480000
#define N_GRAPHS  128
#define D_IN      128
#define D_H       256
#define N_CLASSES 60

// ---------------- scratch (static device globals; no allocation) ------------
__device__ __align__(16) float g_h[(size_t)N_NODES * D_H];  // raw GEMM out y
__device__ __align__(16) float g_a[(size_t)N_NODES * D_H];  // agg out (L1, L3)
__device__ __align__(16) float g_b[(size_t)N_NODES * D_H];  // agg out (L2)
__device__ float g_dinv[N_NODES];
__device__ int   g_degi[N_NODES];
__device__ int   g_cursor[N_NODES];
__device__ int   g_rowptr[N_NODES + 1];
__device__ int   g_srcidx[N_EDGES];
__device__ int   g_part[256];            // scan partials (235 used)
__device__ int   g_gofs[N_GRAPHS + 1];
__device__ float g_pool[N_GRAPHS * D_H];

__device__ __forceinline__ float* buf(int s) {
    return (s == 0) ? g_h : (s == 1) ? g_a : g_b;
}

__device__ __forceinline__ float f2tf(float f) {
    uint32_t u;
    asm("cvt.rna.tf32.f32 %0, %1;" : "=r"(u) : "f"(f));
    return __uint_as_float(u);
}

// ---------------- CSR build --------------------------------------------------
__global__ void k_zero_int() {
    int i = blockIdx.x * blockDim.x + threadIdx.x;
    if (i < N_NODES) { g_degi[i] = 0; g_cursor[i] = 0; }
}

__global__ void k_deg(const int* __restrict__ ei) {
    int t = blockIdx.x * blockDim.x + threadIdx.x;
    if (t * 4 >= N_EDGES) return;
    int4 d4 = *reinterpret_cast<const int4*>(&ei[N_EDGES + t * 4]);
    atomicAdd(&g_degi[d4.x], 1);
    atomicAdd(&g_degi[d4.y], 1);
    atomicAdd(&g_degi[d4.z], 1);
    atomicAdd(&g_degi[d4.w], 1);
}

__global__ void k_dinv() {
    int i = blockIdx.x * blockDim.x + threadIdx.x;
    if (i < N_NODES) g_dinv[i] = rsqrtf((float)(g_degi[i] + 1));  // +1 self loop
}

// --- 3-phase scan: block-local exclusive scan + partial; scan partials; add.
#define SCAN_NB ((N_NODES + 127) / 128)   // 235

__global__ __launch_bounds__(128)
void k_scan1() {
    int t = threadIdx.x, lane = t & 31, w = t >> 5;
    int i = blockIdx.x * 128 + t;
    int v = (i < N_NODES) ? g_degi[i] : 0;
    int x = v;
#pragma unroll
    for (int o = 1; o < 32; o <<= 1) {
        int y = __shfl_up_sync(0xFFFFFFFFu, x, o);
        if (lane >= o) x += y;
    }
    __shared__ int wt[4];
    if (lane == 31) wt[w] = x;
    __syncthreads();
    if (t == 0) {
        int s = 0;
#pragma unroll
        for (int k = 0; k < 4; k++) { int tmp = wt[k]; wt[k] = s; s += tmp; }
        g_part[blockIdx.x] = s;
    }
    __syncthreads();
    if (i < N_NODES) g_rowptr[i] = x - v + wt[w];
}

__global__ __launch_bounds__(256)
void k_scan2() {
    int t = threadIdx.x, lane = t & 31, w = t >> 5;
    int v = (t < SCAN_NB) ? g_part[t] : 0;
    int x = v;
#pragma unroll
    for (int o = 1; o < 32; o <<= 1) {
        int y = __shfl_up_sync(0xFFFFFFFFu, x, o);
        if (lane >= o) x += y;
    }
    __shared__ int wt[8];
    if (lane == 31) wt[w] = x;
    __syncthreads();
    if (t == 0) {
        int s = 0;
#pragma unroll
        for (int k = 0; k < 8; k++) { int tmp = wt[k]; wt[k] = s; s += tmp; }
        g_rowptr[N_NODES] = s;   // total == N_EDGES
    }
    __syncthreads();
    if (t < SCAN_NB) g_part[t] = x - v + wt[w];
}

__global__ void k_scan3() {
    int i = blockIdx.x * blockDim.x + threadIdx.x;
    if (i < N_NODES) g_rowptr[i] += g_part[i >> 7];
}

__global__ void k_fill(const int* __restrict__ ei) {
    int t = blockIdx.x * blockDim.x + threadIdx.x;
    if (t * 4 >= N_EDGES) return;
    int4 s4 = *reinterpret_cast<const int4*>(&ei[t * 4]);
    int4 d4 = *reinterpret_cast<const int4*>(&ei[N_EDGES + t * 4]);
    int p0 = atomicAdd(&g_cursor[d4.x], 1);
    int p1 = atomicAdd(&g_cursor[d4.y], 1);
    int p2 = atomicAdd(&g_cursor[d4.z], 1);
    int p3 = atomicAdd(&g_cursor[d4.w], 1);
    g_srcidx[g_rowptr[d4.x] + p0] = s4.x;
    g_srcidx[g_rowptr[d4.y] + p1] = s4.y;
    g_srcidx[g_rowptr[d4.z] + p2] = s4.z;
    g_srcidx[g_rowptr[d4.w] + p3] = s4.w;
}

// ---------------- TF32 MMA GEMM: g_h = act(A) @ W^T (raw, no dinv) ----------
// Block tile 128x128x32, double-buffered dynamic smem, one sync per K-tile.
#define BM 128
#define BN 128
#define BK 32
#define LDS_W (BK + 4)
#define GEMM_SMEM (4 * BM * LDS_W * 4)   // As0,Ws0,As1,Ws1 in floats*4B

__global__ __launch_bounds__(256)
void k_gemm(const float* __restrict__ Aext, int a_sel,
            const float* __restrict__ W,
            const float* __restrict__ bias, int N, int K) {
    const float* A = Aext ? Aext : buf(a_sel);

    extern __shared__ float sm[];
    float* AsB[2] = { sm,                sm + 2 * BM * LDS_W };
    float* WsB[2] = { sm + BM * LDS_W,   sm + 3 * BM * LDS_W };

    const int tid  = threadIdx.x;
    const int lane = tid & 31;
    const int wid  = tid >> 5;
    const int wm   = (wid & 1) * 64;
    const int wn   = (wid >> 1) * 32;
    const int m0   = blockIdx.x * BM;
    const int n0   = blockIdx.y * BN;
    const int g    = lane >> 2;
    const int t    = lane & 3;
    const int lrow = tid >> 3;
    const int lcol = (tid & 7) * 4;

    float acc[4][4][4];
#pragma unroll
    for (int i = 0; i < 4; i++)
#pragma unroll
        for (int j = 0; j < 4; j++)
#pragma unroll
            for (int c = 0; c < 4; c++) acc[i][j][c] = 0.0f;

    float4 stA[4], stW[4];

    auto ldg_tile = [&](int kt) {
#pragma unroll
        for (int p = 0; p < 4; p++) {
            int row = p * 32 + lrow;
            int ar = m0 + row;
            if (ar < N)
                stA[p] = *reinterpret_cast<const float4*>(&A[(size_t)ar * K + kt + lcol]);
            else
                stA[p] = make_float4(0.f, 0.f, 0.f, 0.f);
            stW[p] = *reinterpret_cast<const float4*>(&W[(size_t)(n0 + row) * K + kt + lcol]);
        }
    };

    auto sts_tile = [&](int kt, float* as, float* ws) {
        float bx = 0.f, by = 0.f, bz = 0.f, bw = 0.f;
        if (bias) {
            bx = bias[kt + lcol + 0]; by = bias[kt + lcol + 1];
            bz = bias[kt + lcol + 2]; bw = bias[kt + lcol + 3];
        }
#pragma unroll
        for (int p = 0; p < 4; p++) {
            int row = p * 32 + lrow;
            float4 v = stA[p];
            if (bias) {
                v.x = fmaxf(v.x + bx, 0.f); v.y = fmaxf(v.y + by, 0.f);
                v.z = fmaxf(v.z + bz, 0.f); v.w = fmaxf(v.w + bw, 0.f);
            }
            float4 cv = make_float4(f2tf(v.x), f2tf(v.y), f2tf(v.z), f2tf(v.w));
            *reinterpret_cast<float4*>(&as[row * LDS_W + lcol]) = cv;
            float4 w = stW[p];
            float4 cw = make_float4(f2tf(w.x), f2tf(w.y), f2tf(w.z), f2tf(w.w));
            *reinterpret_cast<float4*>(&ws[row * LDS_W + lcol]) = cw;
        }
    };

    const int T = K / BK;
    ldg_tile(0);
    sts_tile(0, AsB[0], WsB[0]);
    __syncthreads();

    for (int tt = 0; tt < T; tt++) {
        if (tt + 1 < T) ldg_tile((tt + 1) * BK);

        const float* as = AsB[tt & 1];
        const float* ws = WsB[tt & 1];
#pragma unroll
        for (int ks = 0; ks < 4; ks++) {
            const int kc = ks * 8 + t;
            uint32_t af[4][4], bf[4][2];
#pragma unroll
            for (int i = 0; i < 4; i++) {
                int r = wm + i * 16 + g;
                af[i][0] = __float_as_uint(as[r * LDS_W + kc]);
                af[i][1] = __float_as_uint(as[(r + 8) * LDS_W + kc]);
                af[i][2] = __float_as_uint(as[r * LDS_W + kc + 4]);
                af[i][3] = __float_as_uint(as[(r + 8) * LDS_W + kc + 4]);
            }
#pragma unroll
            for (int j = 0; j < 4; j++) {
                int n = wn + j * 8 + g;
                bf[j][0] = __float_as_uint(ws[n * LDS_W + kc]);
                bf[j][1] = __float_as_uint(ws[n * LDS_W + kc + 4]);
            }
#pragma unroll
            for (int i = 0; i < 4; i++)
#pragma unroll
                for (int j = 0; j < 4; j++) {
                    asm volatile(
                        "mma.sync.aligned.m16n8k8.row.col.f32.tf32.tf32.f32 "
                        "{%0,%1,%2,%3}, {%4,%5,%6,%7}, {%8,%9}, {%0,%1,%2,%3};"
                        : "+f"(acc[i][j][0]), "+f"(acc[i][j][1]),
                          "+f"(acc[i][j][2]), "+f"(acc[i][j][3])
                        : "r"(af[i][0]), "r"(af[i][1]), "r"(af[i][2]), "r"(af[i][3]),
                          "r"(bf[j][0]), "r"(bf[j][1]));
                }
        }
        if (tt + 1 < T) sts_tile((tt + 1) * BK, AsB[(tt + 1) & 1], WsB[(tt + 1) & 1]);
        __syncthreads();
    }

    // epilogue: raw y (no dinv)
#pragma unroll
    for (int i = 0; i < 4; i++) {
        int r0 = m0 + wm + i * 16 + g;
        int r1 = r0 + 8;
#pragma unroll
        for (int j = 0; j < 4; j++) {
            int cc = n0 + wn + j * 8 + t * 2;
            if (r0 < N) {
                float2 v = make_float2(acc[i][j][0], acc[i][j][1]);
                *reinterpret_cast<float2*>(&g_h[(size_t)r0 * D_H + cc]) = v;
            }
            if (r1 < N) {
                float2 v = make_float2(acc[i][j][2], acc[i][j][3]);
                *reinterpret_cast<float2*>(&g_h[(size_t)r1 * D_H + cc]) = v;
            }
        }
    }
}

// ------- pull aggregation: out[d] = dinv[d]*(y[d]*dinv[d] + sum y[s]*dinv[s])
__global__ __launch_bounds__(256)
void k_agg_csr(int out_sel) {
    float* out = buf(out_sel);
    const int d    = blockIdx.x;
    const int tid  = threadIdx.x;
    const int slot = tid >> 6;          // 0..3
    const int cg   = tid & 63;          // float4 channel group
    const int beg  = g_rowptr[d];
    const int end  = g_rowptr[d + 1];
    const float dv = g_dinv[d];

    __shared__ int    s_idx[128];
    __shared__ float  s_dv[128];
    __shared__ float4 s_red[256];

    float4 acc = make_float4(0.f, 0.f, 0.f, 0.f);
    if (slot == 0) {
        float4 v = reinterpret_cast<const float4*>(&g_h[(size_t)d * D_H])[cg];
        acc = make_float4(v.x * dv, v.y * dv, v.z * dv, v.w * dv);
    }

    for (int b = beg; b < end; b += 128) {
        int m = min(128, end - b);
        if (tid < m) {
            int s = g_srcidx[b + tid];
            s_idx[tid] = s;
            s_dv[tid] = g_dinv[s];
        }
        __syncthreads();
        for (int i = slot; i < m; i += 4) {
            float4 v = reinterpret_cast<const float4*>(&g_h[(size_t)s_idx[i] * D_H])[cg];
            float w = s_dv[i];
            acc.x += v.x * w; acc.y += v.y * w; acc.z += v.z * w; acc.w += v.w * w;
        }
        __syncthreads();
    }
    s_red[tid] = acc;
    __syncthreads();
    if (slot == 0) {
        float4 a0 = s_red[cg];
        float4 a1 = s_red[64 + cg];
        float4 a2 = s_red[128 + cg];
        float4 a3 = s_red[192 + cg];
        float4 r;
        r.x = (a0.x + a1.x + a2.x + a3.x) * dv;
        r.y = (a0.y + a1.y + a2.y + a3.y) * dv;
        r.z = (a0.z + a1.z + a2.z + a3.z) * dv;
        r.w = (a0.w + a1.w + a2.w + a3.w) * dv;
        reinterpret_cast<float4*>(&out[(size_t)d * D_H])[cg] = r;
    }
}

// ---------------- pooling (batch is sorted -> contiguous segments) ----------
__global__ void k_gofs(const int* __restrict__ batch) {
    int n = blockIdx.x * blockDim.x + threadIdx.x;
    if (n >= N_NODES) return;
    int b = batch[n];
    int bp = (n == 0) ? -1 : batch[n - 1];
    for (int g = bp + 1; g <= b; g++) g_gofs[g] = n;
    if (n == N_NODES - 1)
        for (int g = b + 1; g <= N_GRAPHS; g++) g_gofs[g] = N_NODES;
}

__global__ __launch_bounds__(256)
void k_pool(const float* __restrict__ b3) {
    int g = blockIdx.x, c = threadIdx.x;
    int beg = g_gofs[g], end = g_gofs[g + 1];
    float bc = b3[c];
    float acc = 0.0f;
    int n = beg;
    for (; n + 4 <= end; n += 4) {
        float v0 = fmaxf(g_a[(size_t)(n + 0) * D_H + c] + bc, 0.f);
        float v1 = fmaxf(g_a[(size_t)(n + 1) * D_H + c] + bc, 0.f);
        float v2 = fmaxf(g_a[(size_t)(n + 2) * D_H + c] + bc, 0.f);
        float v3 = fmaxf(g_a[(size_t)(n + 3) * D_H + c] + bc, 0.f);
        acc += v0 + v1 + v2 + v3;
    }
    for (; n < end; n++) acc += fmaxf(g_a[(size_t)n * D_H + c] + bc, 0.f);
    float cnt = (float)(end - beg);
    g_pool[g * D_H + c] = acc / fmaxf(cnt, 1.0f);
}

// ---------------- final FC ---------------------------------------------------
__global__ void k_fc(const float* __restrict__ Wfc, const float* __restrict__ bfc,
                     float* __restrict__ out) {
    int g = blockIdx.x;
    int c = threadIdx.x;
    if (c >= N_CLASSES) return;
    const float* p = &g_pool[g * D_H];
    const float* w = &Wfc[c * D_H];
    float s = 0.0f;
#pragma unroll 8
    for (int k = 0; k < D_H; k++) s += p[k] * w[k];
    out[g * N_CLASSES + c] = s + bfc[c];
}

// ---------------- launch -----------------------------------------------------
extern "C" void kernel_launch(void* const* d_in, const int* in_sizes, int n_in,
                              void* d_out, int out_size) {
    const float* x    = (const float*)d_in[0];
    const int*   ei   = (const int*)d_in[1];
    const int*   batch= (const int*)d_in[2];
    const float* W1 = (const float*)d_in[3];
    const float* b1 = (const float*)d_in[4];
    const float* W2 = (const float*)d_in[5];
    const float* b2 = (const float*)d_in[6];
    const float* W3 = (const float*)d_in[7];
    const float* b3 = (const float*)d_in[8];
    const float* Wfc= (const float*)d_in[9];
    const float* bfc= (const float*)d_in[10];
    float* out = (float*)d_out;

    const int A = 1, B = 2;

    static bool attr_set = false;
    if (!attr_set) {
        cudaFuncSetAttribute(k_gemm, cudaFuncAttributeMaxDynamicSharedMemorySize,
                             GEMM_SMEM);
        attr_set = true;
    }

    cudaStream_t s1;
    cudaEvent_t e_fork, e_join, e_join2;
    cudaStreamCreateWithFlags(&s1, cudaStreamNonBlocking);
    cudaEventCreateWithFlags(&e_fork, cudaEventDisableTiming);
    cudaEventCreateWithFlags(&e_join, cudaEventDisableTiming);
    cudaEventCreateWithFlags(&e_join2, cudaEventDisableTiming);

    // fork at graph root: side stream builds CSR while main runs gemm1
    cudaEventRecord(e_fork, 0);
    cudaStreamWaitEvent(s1, e_fork, 0);
    k_zero_int<<<(N_NODES + 255) / 256, 256, 0, s1>>>();
    k_deg<<<(N_EDGES / 4 + 255) / 256, 256, 0, s1>>>(ei);
    k_dinv<<<(N_NODES + 255) / 256, 256, 0, s1>>>();
    k_scan1<<<SCAN_NB, 128, 0, s1>>>();
    k_scan2<<<1, 256, 0, s1>>>();
    k_scan3<<<(N_NODES + 255) / 256, 256, 0, s1>>>();
    k_fill<<<(N_EDGES / 4 + 255) / 256, 256, 0, s1>>>(ei);
    cudaEventRecord(e_join, s1);
    // gofs only needed by pool; overlaps the layer pipeline
    k_gofs<<<(N_NODES + 255) / 256, 256, 0, s1>>>(batch);
    cudaEventRecord(e_join2, s1);

    dim3 ggrid((N_NODES + BM - 1) / BM, D_H / BN);
    // main: layer-1 GEMM (independent of CSR/dinv now)
    k_gemm<<<ggrid, 256, GEMM_SMEM>>>(x, 0, W1, nullptr, N_NODES, D_IN);

    cudaStreamWaitEvent(0, e_join, 0);
    k_agg_csr<<<N_NODES, 256>>>(A);
    k_gemm<<<ggrid, 256, GEMM_SMEM>>>(nullptr, A, W2, b1, N_NODES, D_H);
    k_agg_csr<<<N_NODES, 256>>>(B);
    k_gemm<<<ggrid, 256, GEMM_SMEM>>>(nullptr, B, W3, b2, N_NODES, D_H);
    k_agg_csr<<<N_NODES, 256>>>(A);

    cudaStreamWaitEvent(0, e_join2, 0);
    k_pool<<<N_GRAPHS, 256>>>(b3);
    k_fc<<<N_GRAPHS, 64>>>(Wfc, bfc, out);

    cudaEventDestroy(e_fork);
    cudaEventDestroy(e_join);
    cudaEventDestroy(e_join2);
    cudaStreamDestroy(s1);
}

// round 17
// speedup vs baseline: 1.1127x; 1.1127x over previous
#include <cuda_runtime.h>
#include <cuda_bf16.h>
#include <cstdint>

#define N_NODES   30000
#define N_EDGES   480000
#define N_GRAPHS  128
#define D_IN      128
#define D_H       256
#define N_CLASSES 60

// ---------------- scratch (static device globals; no allocation) ------------
__device__ __align__(16) float g_h[(size_t)N_NODES * D_H];  // h' = y*dinv[row]
__device__ __align__(16) float g_a[(size_t)N_NODES * D_H];  // agg out (L1, L3)
__device__ __align__(16) float g_b[(size_t)N_NODES * D_H];  // agg out (L2)
__device__ float g_dinv[N_NODES];
__device__ int   g_degi[N_NODES];
__device__ int   g_cursor[N_NODES];
__device__ int   g_rowptr[N_NODES + 1];
__device__ int   g_srcidx[N_EDGES];
__device__ int   g_part[256];            // scan partials (235 used)
__device__ int   g_gofs[N_GRAPHS + 1];
__device__ float g_pool[N_GRAPHS * D_H];

__device__ __forceinline__ float* buf(int s) {
    return (s == 0) ? g_h : (s == 1) ? g_a : g_b;
}

// round-to-nearest tf32 (unbiased; raw truncation would bias products low)
__device__ __forceinline__ float f2tf(float f) {
    uint32_t u;
    asm("cvt.rna.tf32.f32 %0, %1;" : "=r"(u) : "f"(f));
    return __uint_as_float(u);
}

// ---------------- CSR build --------------------------------------------------
__global__ void k_zero_int() {
    int i = blockIdx.x * blockDim.x + threadIdx.x;
    if (i < N_NODES) { g_degi[i] = 0; g_cursor[i] = 0; }
}

// 4 edges per thread (independent atomic chains; N_EDGES % 4 == 0)
__global__ void k_deg(const int* __restrict__ ei) {
    int t = blockIdx.x * blockDim.x + threadIdx.x;
    if (t * 4 >= N_EDGES) return;
    int4 d4 = *reinterpret_cast<const int4*>(&ei[N_EDGES + t * 4]);
    atomicAdd(&g_degi[d4.x], 1);
    atomicAdd(&g_degi[d4.y], 1);
    atomicAdd(&g_degi[d4.z], 1);
    atomicAdd(&g_degi[d4.w], 1);
}

__global__ void k_dinv() {
    int i = blockIdx.x * blockDim.x + threadIdx.x;
    if (i < N_NODES) g_dinv[i] = rsqrtf((float)(g_degi[i] + 1));  // +1 self loop
}

// --- 3-phase scan: block-local exclusive scan + partial; scan partials; add.
#define SCAN_NB ((N_NODES + 127) / 128)   // 235

__global__ __launch_bounds__(128)
void k_scan1() {
    int t = threadIdx.x, lane = t & 31, w = t >> 5;
    int i = blockIdx.x * 128 + t;
    int v = (i < N_NODES) ? g_degi[i] : 0;
    int x = v;
#pragma unroll
    for (int o = 1; o < 32; o <<= 1) {
        int y = __shfl_up_sync(0xFFFFFFFFu, x, o);
        if (lane >= o) x += y;
    }
    __shared__ int wt[4];
    if (lane == 31) wt[w] = x;
    __syncthreads();
    if (t == 0) {
        int s = 0;
#pragma unroll
        for (int k = 0; k < 4; k++) { int tmp = wt[k]; wt[k] = s; s += tmp; }
        g_part[blockIdx.x] = s;
    }
    __syncthreads();
    if (i < N_NODES) g_rowptr[i] = x - v + wt[w];
}

__global__ __launch_bounds__(256)
void k_scan2() {
    int t = threadIdx.x, lane = t & 31, w = t >> 5;
    int v = (t < SCAN_NB) ? g_part[t] : 0;
    int x = v;
#pragma unroll
    for (int o = 1; o < 32; o <<= 1) {
        int y = __shfl_up_sync(0xFFFFFFFFu, x, o);
        if (lane >= o) x += y;
    }
    __shared__ int wt[8];
    if (lane == 31) wt[w] = x;
    __syncthreads();
    if (t == 0) {
        int s = 0;
#pragma unroll
        for (int k = 0; k < 8; k++) { int tmp = wt[k]; wt[k] = s; s += tmp; }
        g_rowptr[N_NODES] = s;   // total == N_EDGES
    }
    __syncthreads();
    if (t < SCAN_NB) g_part[t] = x - v + wt[w];
}

__global__ void k_scan3() {
    int i = blockIdx.x * blockDim.x + threadIdx.x;
    if (i < N_NODES) g_rowptr[i] += g_part[i >> 7];
}

// 4 edges per thread
__global__ void k_fill(const int* __restrict__ ei) {
    int t = blockIdx.x * blockDim.x + threadIdx.x;
    if (t * 4 >= N_EDGES) return;
    int4 s4 = *reinterpret_cast<const int4*>(&ei[t * 4]);
    int4 d4 = *reinterpret_cast<const int4*>(&ei[N_EDGES + t * 4]);
    int p0 = atomicAdd(&g_cursor[d4.x], 1);
    int p1 = atomicAdd(&g_cursor[d4.y], 1);
    int p2 = atomicAdd(&g_cursor[d4.z], 1);
    int p3 = atomicAdd(&g_cursor[d4.w], 1);
    g_srcidx[g_rowptr[d4.x] + p0] = s4.x;
    g_srcidx[g_rowptr[d4.y] + p1] = s4.y;
    g_srcidx[g_rowptr[d4.z] + p2] = s4.z;
    g_srcidx[g_rowptr[d4.w] + p3] = s4.w;
}

// ---------------- TF32 MMA GEMM: g_h = (act(A) @ W^T) * dinv[row] -----------
// Block tile 128x128x32, 8 warps, warp tile 64x32, mma m16n8k8. (R13 version)
#define BM 128
#define BN 128
#define BK 32

__global__ __launch_bounds__(256)
void k_gemm(const float* __restrict__ Aext, int a_sel,
            const float* __restrict__ W,
            const float* __restrict__ bias, int N, int K) {
    const float* A = Aext ? Aext : buf(a_sel);

    __shared__ float As[BM][BK + 4];
    __shared__ float Ws[BN][BK + 4];

    const int tid  = threadIdx.x;
    const int lane = tid & 31;
    const int wid  = tid >> 5;
    const int wm   = (wid & 1) * 64;
    const int wn   = (wid >> 1) * 32;
    const int m0   = blockIdx.x * BM;
    const int n0   = blockIdx.y * BN;
    const int g    = lane >> 2;
    const int t    = lane & 3;
    const int lrow = tid >> 3;
    const int lcol = (tid & 7) * 4;

    float acc[4][4][4];
#pragma unroll
    for (int i = 0; i < 4; i++)
#pragma unroll
        for (int j = 0; j < 4; j++)
#pragma unroll
            for (int c = 0; c < 4; c++) acc[i][j][c] = 0.0f;

    float4 stA[4], stW[4];

    auto ldg_tile = [&](int kt) {
#pragma unroll
        for (int p = 0; p < 4; p++) {
            int row = p * 32 + lrow;
            int ar = m0 + row;
            if (ar < N)
                stA[p] = *reinterpret_cast<const float4*>(&A[(size_t)ar * K + kt + lcol]);
            else
                stA[p] = make_float4(0.f, 0.f, 0.f, 0.f);
            stW[p] = *reinterpret_cast<const float4*>(&W[(size_t)(n0 + row) * K + kt + lcol]);
        }
    };

    auto sts_tile = [&](int kt) {
        float bx = 0.f, by = 0.f, bz = 0.f, bw = 0.f;
        if (bias) {
            bx = bias[kt + lcol + 0]; by = bias[kt + lcol + 1];
            bz = bias[kt + lcol + 2]; bw = bias[kt + lcol + 3];
        }
#pragma unroll
        for (int p = 0; p < 4; p++) {
            int row = p * 32 + lrow;
            float4 v = stA[p];
            if (bias) {
                v.x = fmaxf(v.x + bx, 0.f); v.y = fmaxf(v.y + by, 0.f);
                v.z = fmaxf(v.z + bz, 0.f); v.w = fmaxf(v.w + bw, 0.f);
            }
            float4 cv = make_float4(f2tf(v.x), f2tf(v.y), f2tf(v.z), f2tf(v.w));
            *reinterpret_cast<float4*>(&As[row][lcol]) = cv;
            float4 w = stW[p];
            float4 cw = make_float4(f2tf(w.x), f2tf(w.y), f2tf(w.z), f2tf(w.w));
            *reinterpret_cast<float4*>(&Ws[row][lcol]) = cw;
        }
    };

    const int T = K / BK;
    ldg_tile(0);
    sts_tile(0);
    __syncthreads();

    for (int tt = 0; tt < T; tt++) {
        if (tt + 1 < T) ldg_tile((tt + 1) * BK);

#pragma unroll
        for (int ks = 0; ks < 4; ks++) {
            const int kc = ks * 8 + t;
            uint32_t af[4][4], bf[4][2];
#pragma unroll
            for (int i = 0; i < 4; i++) {
                int r = wm + i * 16 + g;
                af[i][0] = __float_as_uint(As[r][kc]);
                af[i][1] = __float_as_uint(As[r + 8][kc]);
                af[i][2] = __float_as_uint(As[r][kc + 4]);
                af[i][3] = __float_as_uint(As[r + 8][kc + 4]);
            }
#pragma unroll
            for (int j = 0; j < 4; j++) {
                int n = wn + j * 8 + g;
                bf[j][0] = __float_as_uint(Ws[n][kc]);
                bf[j][1] = __float_as_uint(Ws[n][kc + 4]);
            }
#pragma unroll
            for (int i = 0; i < 4; i++)
#pragma unroll
                for (int j = 0; j < 4; j++) {
                    asm volatile(
                        "mma.sync.aligned.m16n8k8.row.col.f32.tf32.tf32.f32 "
                        "{%0,%1,%2,%3}, {%4,%5,%6,%7}, {%8,%9}, {%0,%1,%2,%3};"
                        : "+f"(acc[i][j][0]), "+f"(acc[i][j][1]),
                          "+f"(acc[i][j][2]), "+f"(acc[i][j][3])
                        : "r"(af[i][0]), "r"(af[i][1]), "r"(af[i][2]), "r"(af[i][3]),
                          "r"(bf[j][0]), "r"(bf[j][1]));
                }
        }
        __syncthreads();
        if (tt + 1 < T) sts_tile((tt + 1) * BK);
        __syncthreads();
    }

#pragma unroll
    for (int i = 0; i < 4; i++) {
        int r0 = m0 + wm + i * 16 + g;
        int r1 = r0 + 8;
        float dv0 = (r0 < N) ? g_dinv[r0] : 0.f;
        float dv1 = (r1 < N) ? g_dinv[r1] : 0.f;
#pragma unroll
        for (int j = 0; j < 4; j++) {
            int cc = n0 + wn + j * 8 + t * 2;
            if (r0 < N) {
                float2 v = make_float2(acc[i][j][0] * dv0, acc[i][j][1] * dv0);
                *reinterpret_cast<float2*>(&g_h[(size_t)r0 * D_H + cc]) = v;
            }
            if (r1 < N) {
                float2 v = make_float2(acc[i][j][2] * dv1, acc[i][j][3] * dv1);
                *reinterpret_cast<float2*>(&g_h[(size_t)r1 * D_H + cc]) = v;
            }
        }
    }
}

// ------- pull aggregation: out[d] = dinv[d]*(h'[d] + sum h'[src]) -----------
// 256 threads = 4 edge-slots x 64 channel-groups (float4 each)  (R13 version)
__global__ __launch_bounds__(256)
void k_agg_csr(int out_sel) {
    float* out = buf(out_sel);
    const int d    = blockIdx.x;
    const int tid  = threadIdx.x;
    const int slot = tid >> 6;          // 0..3
    const int cg   = tid & 63;          // float4 channel group
    const int beg  = g_rowptr[d];
    const int end  = g_rowptr[d + 1];

    __shared__ int    s_idx[128];
    __shared__ float4 s_red[256];

    float4 acc = make_float4(0.f, 0.f, 0.f, 0.f);
    if (slot == 0)
        acc = reinterpret_cast<const float4*>(&g_h[(size_t)d * D_H])[cg];

    for (int b = beg; b < end; b += 128) {
        int m = min(128, end - b);
        if (tid < m) s_idx[tid] = g_srcidx[b + tid];
        __syncthreads();
        for (int i = slot; i < m; i += 4) {
            float4 v = reinterpret_cast<const float4*>(&g_h[(size_t)s_idx[i] * D_H])[cg];
            acc.x += v.x; acc.y += v.y; acc.z += v.z; acc.w += v.w;
        }
        __syncthreads();
    }
    s_red[tid] = acc;
    __syncthreads();
    if (slot == 0) {
        float4 a0 = s_red[cg];
        float4 a1 = s_red[64 + cg];
        float4 a2 = s_red[128 + cg];
        float4 a3 = s_red[192 + cg];
        float dv = g_dinv[d];
        float4 r;
        r.x = (a0.x + a1.x + a2.x + a3.x) * dv;
        r.y = (a0.y + a1.y + a2.y + a3.y) * dv;
        r.z = (a0.z + a1.z + a2.z + a3.z) * dv;
        r.w = (a0.w + a1.w + a2.w + a3.w) * dv;
        reinterpret_cast<float4*>(&out[(size_t)d * D_H])[cg] = r;
    }
}

// ---------------- pooling (batch is sorted -> contiguous segments) ----------
__global__ void k_gofs(const int* __restrict__ batch) {
    int n = blockIdx.x * blockDim.x + threadIdx.x;
    if (n >= N_NODES) return;
    int b = batch[n];
    int bp = (n == 0) ? -1 : batch[n - 1];
    for (int g = bp + 1; g <= b; g++) g_gofs[g] = n;
    if (n == N_NODES - 1)
        for (int g = b + 1; g <= N_GRAPHS; g++) g_gofs[g] = N_NODES;
}

__global__ __launch_bounds__(256)
void k_pool(const float* __restrict__ b3) {
    int g = blockIdx.x, c = threadIdx.x;
    int beg = g_gofs[g], end = g_gofs[g + 1];
    float bc = b3[c];
    float acc = 0.0f;
    int n = beg;
    for (; n + 4 <= end; n += 4) {
        float v0 = fmaxf(g_a[(size_t)(n + 0) * D_H + c] + bc, 0.f);
        float v1 = fmaxf(g_a[(size_t)(n + 1) * D_H + c] + bc, 0.f);
        float v2 = fmaxf(g_a[(size_t)(n + 2) * D_H + c] + bc, 0.f);
        float v3 = fmaxf(g_a[(size_t)(n + 3) * D_H + c] + bc, 0.f);
        acc += v0 + v1 + v2 + v3;
    }
    for (; n < end; n++) acc += fmaxf(g_a[(size_t)n * D_H + c] + bc, 0.f);
    float cnt = (float)(end - beg);
    g_pool[g * D_H + c] = acc / fmaxf(cnt, 1.0f);
}

// ---------------- final FC ---------------------------------------------------
__global__ void k_fc(const float* __restrict__ Wfc, const float* __restrict__ bfc,
                     float* __restrict__ out) {
    int g = blockIdx.x;
    int c = threadIdx.x;
    if (c >= N_CLASSES) return;
    const float* p = &g_pool[g * D_H];
    const float* w = &Wfc[c * D_H];
    float s = 0.0f;
#pragma unroll 8
    for (int k = 0; k < D_H; k++) s += p[k] * w[k];
    out[g * N_CLASSES + c] = s + bfc[c];
}

// ---------------- launch -----------------------------------------------------
extern "C" void kernel_launch(void* const* d_in, const int* in_sizes, int n_in,
                              void* d_out, int out_size) {
    const float* x    = (const float*)d_in[0];
    const int*   ei   = (const int*)d_in[1];
    const int*   batch= (const int*)d_in[2];
    const float* W1 = (const float*)d_in[3];
    const float* b1 = (const float*)d_in[4];
    const float* W2 = (const float*)d_in[5];
    const float* b2 = (const float*)d_in[6];
    const float* W3 = (const float*)d_in[7];
    const float* b3 = (const float*)d_in[8];
    const float* Wfc= (const float*)d_in[9];
    const float* bfc= (const float*)d_in[10];
    float* out = (float*)d_out;

    const int A = 1, B = 2;

    // fork/join plumbing (host-side objects; not in the replayed graph)
    cudaStream_t s1;
    cudaEvent_t e_fork, e_join;
    cudaStreamCreateWithFlags(&s1, cudaStreamNonBlocking);
    cudaEventCreateWithFlags(&e_fork, cudaEventDisableTiming);
    cudaEventCreateWithFlags(&e_join, cudaEventDisableTiming);

    // main stream: degree (needed by dinv AND scan)
    k_zero_int<<<(N_NODES + 255) / 256, 256>>>();
    k_deg<<<(N_EDGES / 4 + 255) / 256, 256>>>(ei);
    cudaEventRecord(e_fork, 0);

    // side stream: CSR scan/fill + pool offsets (overlaps dinv + gemm1)
    cudaStreamWaitEvent(s1, e_fork, 0);
    k_scan1<<<SCAN_NB, 128, 0, s1>>>();
    k_scan2<<<1, 256, 0, s1>>>();
    k_scan3<<<(N_NODES + 255) / 256, 256, 0, s1>>>();
    k_fill<<<(N_EDGES / 4 + 255) / 256, 256, 0, s1>>>(ei);
    k_gofs<<<(N_NODES + 255) / 256, 256, 0, s1>>>(batch);
    cudaEventRecord(e_join, s1);

    // main stream: dinv then layer-1 GEMM
    k_dinv<<<(N_NODES + 255) / 256, 256>>>();
    dim3 ggrid((N_NODES + BM - 1) / BM, D_H / BN);
    k_gemm<<<ggrid, 256>>>(x, 0, W1, nullptr, N_NODES, D_IN);

    // join: aggregation needs CSR
    cudaStreamWaitEvent(0, e_join, 0);
    k_agg_csr<<<N_NODES, 256>>>(A);
    // layer 2
    k_gemm<<<ggrid, 256>>>(nullptr, A, W2, b1, N_NODES, D_H);
    k_agg_csr<<<N_NODES, 256>>>(B);
    // layer 3
    k_gemm<<<ggrid, 256>>>(nullptr, B, W3, b2, N_NODES, D_H);
    k_agg_csr<<<N_NODES, 256>>>(A);

    // pool + fc
    k_pool<<<N_GRAPHS, 256>>>(b3);
    k_fc<<<N_GRAPHS, 64>>>(Wfc, bfc, out);

    cudaEventDestroy(e_fork);
    cudaEventDestroy(e_join);
    cudaStreamDestroy(s1);
}